// round 11
// baseline (speedup 1.0000x reference)
#include <cuda_runtime.h>
#include <cuda_bf16.h>

// ---- static problem config ----
#define NIMG 32
#define HH   1024
#define WW   1024
#define BHW  16                 // pool window
#define BSTR 14                 // block stride
#define BC   73                 // blocks per spatial dim
#define BC2  (BC*BC)            // 5329
#define NROW (NIMG*BC)          // 2336  (n, bh) row-blocks
#define NBLK (NROW*BC)          // 170528 total blocks
#define OUT_ELEMS (NBLK*3)      // 511584 floats = 127896 float4 (exact)
#define OUT_VEC4  (OUT_ELEMS/4)
#define THRESH 0.9f
#define W4     (WW/4)

// scratch (device globals — no allocation allowed; zero-initialized)
__device__ unsigned g_bitmap[NROW * 3];   // 96-bit active mask per (n,bh) row
__device__ unsigned g_count[NROW];        // popcount per row
__device__ unsigned g_acc;                // sum of counts (reset by last CTA)
__device__ unsigned g_done;               // completion counter (reset by last CTA)

// ---------------------------------------------------------------------------
// helpers
// ---------------------------------------------------------------------------
__device__ __forceinline__ int nth_set_bit(unsigned w, int n)  // n-th (0-based)
{
    return (int)__fns(w, 0, n + 1);
}

__device__ __forceinline__ void resolve_dense(unsigned p,
                                              float& x, float& y, float& z)
{
    unsigned n = p / BC2;
    unsigned r = p - n * BC2;
    x = (float)n;
    y = (float)(r / BC);
    z = (float)(r % BC);
}

__device__ __forceinline__ float4 phase_pack(int phase,
                                             float a0, float a1, float a2,
                                             float b0, float b1, float b2)
{
    if (phase == 0) return make_float4(a0, a1, a2, b0);
    if (phase == 1) return make_float4(a1, a2, b0, b1);
    return make_float4(a2, b0, b1, b2);
}

// Cold sparse fallback: last CTA rewrites the ENTIRE output using an smem
// exclusive scan of the per-row counts + bitmap bit-ranking. Never executes
// on the bench input (every block is active); kept for correctness.
__device__ __noinline__ void sparse_rewrite(float4* __restrict__ out,
                                            unsigned* __restrict__ s_off,
                                            unsigned* __restrict__ s_part,
                                            unsigned total, int tid)
{
    const int CH = (NROW + 255) / 256;    // 10
    for (int i = tid; i < NROW; i += 256) s_off[i] = g_count[i];
    __syncthreads();

    const int start = tid * CH;
    const int end   = (start + CH < NROW) ? (start + CH) : NROW;
    unsigned sum = 0;
    for (int i = start; i < end; ++i) sum += s_off[i];
    s_part[tid] = sum;
    __syncthreads();
    for (int off = 1; off < 256; off <<= 1) {
        unsigned t = (tid >= off) ? s_part[tid - off] : 0u;
        __syncthreads();
        s_part[tid] += t;
        __syncthreads();
    }
    unsigned run = (tid > 0) ? s_part[tid - 1] : 0u;
    for (int i = start; i < end; ++i) {
        unsigned c = s_off[i];
        s_off[i] = run;
        run += c;
    }
    __syncthreads();

    for (int slot = tid; slot < OUT_VEC4; slot += 256) {
        const unsigned p0 = ((unsigned)slot * 4u) / 3u;
        float t[6];
        #pragma unroll
        for (int q = 0; q < 2; ++q) {
            unsigned p = p0 + (unsigned)q;
            float *x = &t[3 * q];
            if (p >= total) { x[0] = -1.f; x[1] = -1.f; x[2] = -1.f; continue; }
            int lo = 0, hi = NROW - 1;
            while (lo < hi) {
                int mid = (lo + hi + 1) >> 1;
                if (s_off[mid] <= p) lo = mid; else hi = mid - 1;
            }
            int rank = (int)(p - s_off[lo]);
            unsigned w0 = g_bitmap[lo * 3 + 0];
            unsigned w1 = g_bitmap[lo * 3 + 1];
            unsigned w2 = g_bitmap[lo * 3 + 2];
            int c0 = __popc(w0), c1 = __popc(w1);
            int bw;
            if (rank < c0)            bw = nth_set_bit(w0, rank);
            else if (rank - c0 < c1)  bw = 32 + nth_set_bit(w1, rank - c0);
            else                      bw = 64 + nth_set_bit(w2, rank - c0 - c1);
            x[0] = (float)(lo / BC);
            x[1] = (float)(lo % BC);
            x[2] = (float)bw;
        }
        out[slot] = phase_pack(slot % 3, t[0], t[1], t[2], t[3], t[4], t[5]);
    }
}

// ---------------------------------------------------------------------------
// Fused kernel: one CTA per (n, bh).
//  1. Speculative dense output store (slot = global thread id): the dense
//     result is a pure function of the index — independent of pooling.
//  2. Pool body (exact R5 structure: occ 93.5%, DRAM ~71%).
//  3. threadFenceReduction tail: last CTA verifies total == NBLK (always on
//     this input) or rewrites the output sparse; resets counters for replay.
// ---------------------------------------------------------------------------
__global__ __launch_bounds__(256, 8)
void fused_kernel(const float* __restrict__ mask, float4* __restrict__ out)
{
    const int cta = blockIdx.x;          // n*BC + bh
    const int n   = cta / BC;
    const int bh  = cta % BC;
    const int tid = threadIdx.x;

    __shared__ float    sv[WW];
    __shared__ unsigned sbm[3];
    __shared__ unsigned s_off[NROW];     // sparse fallback only
    __shared__ unsigned s_part[256];     // sparse fallback only
    __shared__ unsigned s_total;
    __shared__ bool     s_last;

    // ---- 1. speculative dense store ----
    {
        const int slot = cta * 256 + tid;
        if (slot < OUT_VEC4) {
            const unsigned p0 = ((unsigned)slot * 4u) / 3u;
            float a0, a1, a2, b0, b1, b2;
            resolve_dense(p0,      a0, a1, a2);
            resolve_dense(p0 + 1u, b0, b1, b2);   // p0+1 <= 170527 < NBLK
            out[slot] = phase_pack(slot % 3, a0, a1, a2, b0, b1, b2);
        }
    }

    // ---- 2. pool body (R5-proven) ----
    // padded window [bh*14, bh*14+16) -> unpadded rows [bh*14-1, bh*14+15)
    const int h0 = bh * BSTR - 1;
    const int hs = (h0 < 0) ? 0 : h0;
    const int he = (h0 + BHW < HH) ? (h0 + BHW) : HH;

    const float4* base = (const float4*)(mask + (size_t)n * HH * WW);
    float4 acc = make_float4(0.f, 0.f, 0.f, 0.f);
    #pragma unroll 4
    for (int h = hs; h < he; ++h) {
        float4 x = base[h * W4 + tid];
        acc.x = fmaxf(acc.x, x.x);
        acc.y = fmaxf(acc.y, x.y);
        acc.z = fmaxf(acc.z, x.z);
        acc.w = fmaxf(acc.w, x.w);
    }
    sv[4 * tid + 0] = acc.x;
    sv[4 * tid + 1] = acc.y;
    sv[4 * tid + 2] = acc.z;
    sv[4 * tid + 3] = acc.w;
    __syncthreads();

    if (tid < 96) {                       // warps 0,1,2
        float m = 0.f;
        if (tid < BC) {
            const int w0 = tid * BSTR - 1;
            const int ws = (w0 < 0) ? 0 : w0;
            const int we = (w0 + BHW < WW) ? (w0 + BHW) : WW;
            for (int w = ws; w < we; ++w) m = fmaxf(m, sv[w]);
        }
        unsigned b = __ballot_sync(0xFFFFFFFFu, m > THRESH);
        if ((tid & 31) == 0) sbm[tid >> 5] = b;
    }
    __syncthreads();

    if (tid < 3) g_bitmap[cta * 3 + tid] = sbm[tid];

    // ---- 3. fence + atomic completion tail ----
    if (tid == 0) {
        unsigned c = (unsigned)(__popc(sbm[0]) + __popc(sbm[1]) + __popc(sbm[2]));
        g_count[cta] = c;
        __threadfence();                  // publish bitmap/count
        atomicAdd(&g_acc, c);
        __threadfence();                  // order acc before done
        unsigned prev = atomicAdd(&g_done, 1u);
        s_last = (prev == (unsigned)(NROW - 1));
    }
    __syncthreads();
    if (!s_last) return;

    // last CTA: all bitmaps/counts/acc visible (fence+atomic chain)
    if (tid == 0) {
        s_total = g_acc;
        g_acc  = 0;                       // reset for next graph replay
        g_done = 0;
    }
    __syncthreads();

    if (s_total == NBLK) return;          // dense: speculative output correct

    sparse_rewrite(out, s_off, s_part, s_total, tid);   // never on this input
}

// ---------------------------------------------------------------------------
extern "C" void kernel_launch(void* const* d_in, const int* in_sizes, int n_in,
                              void* d_out, int out_size)
{
    const float* mask = (const float*)d_in[0];

    fused_kernel<<<NROW, 256>>>(mask, (float4*)d_out);
}

// round 12
// speedup vs baseline: 2.2425x; 2.2425x over previous
#include <cuda_runtime.h>
#include <cuda_bf16.h>

// ---- static problem config ----
#define NIMG 32
#define HH   1024
#define WW   1024
#define BHW  16                 // pool window
#define BSTR 14                 // block stride
#define BC   73                 // blocks per spatial dim
#define BC2  (BC*BC)            // 5329
#define NROW (NIMG*BC)          // 2336  (n, bh) row-blocks
#define NBLK (NROW*BC)          // 170528 total blocks
#define OUT_ELEMS (NBLK*3)      // 511584 floats = 127896 float4 (exact)
#define OUT_VEC4  (OUT_ELEMS/4)
#define THRESH 0.9f
#define W4     (WW/4)

// scratch (device globals — no allocation allowed)
__device__ unsigned g_bitmap[NROW * 3];   // 96-bit active mask per (n,bh) row
__device__ unsigned g_count[NROW];        // popcount per row

__device__ __forceinline__ float4 fmax4(float4 a, float4 b)
{
    return make_float4(fmaxf(a.x, b.x), fmaxf(a.y, b.y),
                       fmaxf(a.z, b.z), fmaxf(a.w, b.w));
}

// ---------------------------------------------------------------------------
// K1: one CTA per (n, bh), R5 memory structure + MONOTONE EARLY EXIT.
// A block is active iff ANY pixel in its 16x16 window exceeds THRESH; the
// bitmap is monotone in the number of rows processed. So: consume the <=16
// rows in chunks of 4; after each chunk run the horizontal-max + ballot
// phase; if all 73 windows are already active, the remaining rows cannot
// change the answer -> break. On uniform data ~92% of CTAs stop after 4
// rows (expected ~4.3 rows instead of 16 -> ~3.4x less DRAM traffic).
// Correct for ANY input: without early exit it degenerates to the full scan.
// Zero is the exact identity (zero padding, mask values in [0,1)).
// ---------------------------------------------------------------------------
__global__ __launch_bounds__(256) void pool_kernel(const float* __restrict__ mask)
{
    const int cta = blockIdx.x;          // n*BC + bh
    const int n   = cta / BC;
    const int bh  = cta % BC;
    const int tid = threadIdx.x;

    __shared__ float4   sv4[256];        // per-column running max (1024 cols)
    __shared__ unsigned sbm[3];

    // padded window [bh*14, bh*14+16) -> unpadded rows [bh*14-1, bh*14+15)
    const int h0 = bh * BSTR - 1;
    const int hs = (h0 < 0) ? 0 : h0;
    const int he = (h0 + BHW < HH) ? (h0 + BHW) : HH;
    const int total_rows = he - hs;      // 15 (bh==0) or 16

    const float4* base = (const float4*)(mask + (size_t)n * HH * WW) + hs * W4 + tid;

    float4 acc = make_float4(0.f, 0.f, 0.f, 0.f);
    int processed = 0;

    for (;;) {
        const int remaining = total_rows - processed;
        if (remaining >= 4) {
            // front-batched 4-row chunk (MLP=4, same as proven R5 loop)
            float4 x0 = base[(processed + 0) * W4];
            float4 x1 = base[(processed + 1) * W4];
            float4 x2 = base[(processed + 2) * W4];
            float4 x3 = base[(processed + 3) * W4];
            acc = fmax4(acc, fmax4(fmax4(x0, x1), fmax4(x2, x3)));
            processed += 4;
        } else {
            for (int i = 0; i < remaining; ++i)
                acc = fmax4(acc, base[(processed + i) * W4]);
            processed = total_rows;
        }

        // checkpoint: horizontal phase over current column maxima
        sv4[tid] = acc;
        __syncthreads();
        const float* sv = (const float*)sv4;
        if (tid < 96) {                   // warps 0,1,2
            float m = 0.f;
            if (tid < BC) {
                const int w0 = tid * BSTR - 1;
                const int ws = (w0 < 0) ? 0 : w0;
                const int we = (w0 + BHW < WW) ? (w0 + BHW) : WW;
                for (int w = ws; w < we; ++w) m = fmaxf(m, sv[w]);
            }
            unsigned b = __ballot_sync(0xFFFFFFFFu, m > THRESH);
            if ((tid & 31) == 0) sbm[tid >> 5] = b;
        }
        __syncthreads();

        const bool all_active = (sbm[0] == 0xFFFFFFFFu) &
                                (sbm[1] == 0xFFFFFFFFu) &
                                (sbm[2] == 0x1FFu);
        if (all_active || processed >= total_rows) break;
        // continuing: every thread passed the sync above, so rewriting sv4
        // next iteration cannot race the readers of this checkpoint.
    }

    if (tid < 3) g_bitmap[cta * 3 + tid] = sbm[tid];
    if (tid == 0)
        g_count[cta] = (unsigned)(__popc(sbm[0]) + __popc(sbm[1]) + __popc(sbm[2]));
}

// ---------------------------------------------------------------------------
// K2: write (exact R10 structure — 2.7us wall). Phase A: SUM of the 2336
// counts -> total. Dense path (total == NBLK): pure divmod, no offsets.
// Sparse fallback: full smem scan + bitmap bit-ranking (never taken here).
// Phase B: 2 float4 slots per thread, register-triple phase branch.
// ---------------------------------------------------------------------------
#define WT      256
#define WSLOTS  2
#define WGRID   ((OUT_VEC4 + WT*WSLOTS - 1) / (WT*WSLOTS))   // 250
#define WCHUNK  ((NROW + WT - 1) / WT)    // 10

__device__ __forceinline__ int nth_set_bit(unsigned w, int n)  // n-th (0-based)
{
    return (int)__fns(w, 0, n + 1);
}

__device__ __forceinline__ void resolve_dense(unsigned p,
                                              float& x, float& y, float& z)
{
    unsigned n = p / BC2;
    unsigned r = p - n * BC2;
    x = (float)n;
    y = (float)(r / BC);
    z = (float)(r % BC);
}

__device__ __forceinline__ void resolve_gen(unsigned p, unsigned total,
                                            const unsigned* __restrict__ s_off,
                                            float& x, float& y, float& z)
{
    if (p >= total) { x = -1.f; y = -1.f; z = -1.f; return; }

    int lo = 0, hi = NROW - 1;
    while (lo < hi) {
        int mid = (lo + hi + 1) >> 1;
        if (s_off[mid] <= p) lo = mid; else hi = mid - 1;
    }
    const int row  = lo;
    int       rank = (int)(p - s_off[row]);

    unsigned w0 = g_bitmap[row * 3 + 0];
    unsigned w1 = g_bitmap[row * 3 + 1];
    unsigned w2 = g_bitmap[row * 3 + 2];
    int c0 = __popc(w0), c1 = __popc(w1);
    int bw;
    if (rank < c0)            bw = nth_set_bit(w0, rank);
    else if (rank - c0 < c1)  bw = 32 + nth_set_bit(w1, rank - c0);
    else                      bw = 64 + nth_set_bit(w2, rank - c0 - c1);

    x = (float)(row / BC);
    y = (float)(row % BC);
    z = (float)bw;
}

__device__ __forceinline__ float4 phase_pack(int phase,
                                             float a0, float a1, float a2,
                                             float b0, float b1, float b2)
{
    if (phase == 0) return make_float4(a0, a1, a2, b0);
    if (phase == 1) return make_float4(a1, a2, b0, b1);
    return make_float4(a2, b0, b1, b2);
}

__global__ __launch_bounds__(WT) void write_kernel(float4* __restrict__ out)
{
    __shared__ unsigned s_off[NROW];          // sparse fallback only
    __shared__ unsigned s_wsum[WT / 32];
    __shared__ unsigned s_total;

    const int tid = threadIdx.x;

    // ---- Phase A: total = sum(g_count) ----
    unsigned v = 0;
    #pragma unroll
    for (int k = 0; k < WCHUNK; ++k) {
        int i = k * WT + tid;
        if (i < NROW) v += g_count[i];
    }
    #pragma unroll
    for (int o = 16; o >= 1; o >>= 1)
        v += __shfl_down_sync(0xFFFFFFFFu, v, o);
    if ((tid & 31) == 0) s_wsum[tid >> 5] = v;
    __syncthreads();
    if (tid == 0) {
        unsigned t = 0;
        #pragma unroll
        for (int w = 0; w < WT / 32; ++w) t += s_wsum[w];
        s_total = t;
    }
    __syncthreads();
    const unsigned total = s_total;

    const bool dense = (total == NBLK);
    if (!dense) {
        // ---- sparse fallback: full exclusive scan into s_off ----
        for (int i = tid; i < NROW; i += WT) s_off[i] = g_count[i];
        __syncthreads();
        __shared__ unsigned s_part[WT];
        const int start = tid * WCHUNK;
        const int end   = (start + WCHUNK < NROW) ? (start + WCHUNK) : NROW;
        unsigned sum = 0;
        for (int i = start; i < end; ++i) sum += s_off[i];
        s_part[tid] = sum;
        __syncthreads();
        for (int off = 1; off < WT; off <<= 1) {
            unsigned t = (tid >= off) ? s_part[tid - off] : 0u;
            __syncthreads();
            s_part[tid] += t;
            __syncthreads();
        }
        unsigned run = (tid > 0) ? s_part[tid - 1] : 0u;
        for (int i = start; i < end; ++i) {
            unsigned c = s_off[i];
            s_off[i] = run;
            run += c;
        }
        __syncthreads();
    }

    // ---- Phase B: WSLOTS float4 slots per thread ----
    #pragma unroll
    for (int k = 0; k < WSLOTS; ++k) {
        const int slot = (blockIdx.x * WSLOTS + k) * WT + tid;
        if (slot >= OUT_VEC4) continue;

        const unsigned p0 = ((unsigned)slot * 4u) / 3u;
        float a0, a1, a2, b0, b1, b2;
        if (dense) {
            resolve_dense(p0, a0, a1, a2);
            if (p0 + 1u < NBLK) resolve_dense(p0 + 1u, b0, b1, b2);
            else { b0 = -1.f; b1 = -1.f; b2 = -1.f; }
        } else {
            resolve_gen(p0,      total, s_off, a0, a1, a2);
            resolve_gen(p0 + 1u, total, s_off, b0, b1, b2);
        }

        out[slot] = phase_pack(slot % 3, a0, a1, a2, b0, b1, b2);
    }
}

// ---------------------------------------------------------------------------
extern "C" void kernel_launch(void* const* d_in, const int* in_sizes, int n_in,
                              void* d_out, int out_size)
{
    const float* mask = (const float*)d_in[0];

    pool_kernel<<<NROW, 256>>>(mask);
    write_kernel<<<WGRID, WT>>>((float4*)d_out);
}